// round 14
// baseline (speedup 1.0000x reference)
#include <cuda_runtime.h>
#include <cuda_fp16.h>
#include <mma.h>
using namespace nvcuda;

#define MAXN 100000
#define MAXE 1600000
#define HIDF 64

// ---------------- static device scratch ----------------
__device__ __align__(16) float d_hw[(size_t)MAXN * HIDF];    // fp16 rows (N x 64 halves)
__device__ __align__(16) float d_hbuf[(size_t)MAXN * HIDF];  // aggregated features fp32
__device__ int   d_cnt[MAXN];
__device__ int   d_fill[MAXN];
__device__ int   d_off[MAXN + 1];
__device__ float d_dinv[MAXN];
__device__ int2  d_csr[MAXE];
__device__ int   d_bsum[128];
__device__ float d_stats[256];      // two dense buffers of 128: [sum64|sumsq64] x2

// ---- aux stream/events, created pre-main (outside any mem checkpoint / capture) ----
struct StreamInit {
    cudaStream_t s = nullptr;
    cudaEvent_t  ef = nullptr, ej = nullptr;
    bool ok = false;
    StreamInit() {
        if (cudaStreamCreateWithFlags(&s, cudaStreamNonBlocking) == cudaSuccess &&
            cudaEventCreateWithFlags(&ef, cudaEventDisableTiming) == cudaSuccess &&
            cudaEventCreateWithFlags(&ej, cudaEventDisableTiming) == cudaSuccess)
            ok = true;
    }
};
static StreamInit g_si;

// ---------------- CSR construction ----------------
__global__ void zero_kernel(int N) {
    int i = blockIdx.x * blockDim.x + threadIdx.x;
    if (i < N) d_cnt[i] = 0;
}

__global__ void hist_kernel(const int* __restrict__ dst, int E) {
    int i = blockIdx.x * blockDim.x + threadIdx.x;
    if (i < E) atomicAdd(&d_cnt[dst[i]], 1);
}

__global__ void scanA_kernel(int N) {
    __shared__ int sh[256];
    int base = blockIdx.x * 1024 + threadIdx.x * 4;
    int t = 0;
#pragma unroll
    for (int j = 0; j < 4; j++) {
        int i = base + j;
        if (i < N) {
            int c = d_cnt[i];
            t += c;
            d_dinv[i] = rsqrtf((float)(c + 1));
        }
    }
    sh[threadIdx.x] = t;
    __syncthreads();
    for (int o = 128; o > 0; o >>= 1) {
        if (threadIdx.x < o) sh[threadIdx.x] += sh[threadIdx.x + o];
        __syncthreads();
    }
    if (threadIdx.x == 0) d_bsum[blockIdx.x] = sh[0];
}

__global__ void scanC_kernel(int G, int N) {
    __shared__ int sh[256];
    __shared__ int bs[128];
    __shared__ int bprefix;
    int tid = threadIdx.x;
    if (tid < G) bs[tid] = d_bsum[tid];
    __syncthreads();
    if (tid == 0) {
        int p = 0;
        for (int b = 0; b < (int)blockIdx.x; b++) p += bs[b];
        bprefix = p;
    }
    int base = blockIdx.x * 1024 + tid * 4;
    int v[4]; int t = 0;
#pragma unroll
    for (int j = 0; j < 4; j++) { v[j] = (base + j < N) ? d_cnt[base + j] : 0; t += v[j]; }
    sh[tid] = t;
    __syncthreads();
    for (int o = 1; o < 256; o <<= 1) {
        int x = (tid >= o) ? sh[tid - o] : 0;
        __syncthreads();
        sh[tid] += x;
        __syncthreads();
    }
    int excl = sh[tid] - t + bprefix;
#pragma unroll
    for (int j = 0; j < 4; j++) {
        if (base + j < N) { d_off[base + j] = excl; d_fill[base + j] = 0; excl += v[j]; }
    }
    if ((int)blockIdx.x == G - 1 && tid == 255) d_off[N] = bprefix + sh[255];
}

__global__ void scatter_kernel(const int* __restrict__ src,
                               const int* __restrict__ dst, int E) {
    int i = blockIdx.x * blockDim.x + threadIdx.x;
    if (i >= E) return;
    int s = src[i];
    int d = dst[i];
    int pos = d_off[d] + atomicAdd(&d_fill[d], 1);
    float w = d_dinv[s] * d_dinv[d];
    d_csr[pos] = make_int2(s, __float_as_int(w));
}

__device__ __forceinline__ void split_h2(float a, float b, half2& hi, half2& lo) {
    half2 h = __floats2half2_rn(a, b);
    float2 hf = __half22float2(h);
    hi = h;
    lo = __floats2half2_rn(a - hf.x, b - hf.y);
}

__device__ __forceinline__ unsigned h2u(half2 h) { return *(unsigned*)&h; }

// ---------------- split-fp16 wmma GEMM, register-prefetch pipelined ----------------
template <int K, int NC, bool USE_X, bool BNIN, bool DOT>
__global__ void __launch_bounds__(128) gemm_kernel(
        const float* __restrict__ A_ext, const float* __restrict__ Wm,
        const float* __restrict__ g, const float* __restrict__ bt,
        const float* __restrict__ lb1, const float* __restrict__ lw2,
        const float* __restrict__ lb2, float* __restrict__ out,
        int M, int bnoff, int zsoff) {
    constexpr int ROWS = 64;
    constexpr int CH = 32;
    constexpr int NCHUNK = K / CH;
    constexpr int LDA = CH + 8;
    constexpr int LDB = NC + 8;
    constexpr int LDC = NC + 4;
    constexpr int WF4 = CH * NC / (4 * 128);
    constexpr int A_HALVES = ROWS * LDA;
    constexpr int W_HALVES = CH * LDB;
    constexpr int AB_BYTES = (2 * A_HALVES + 2 * W_HALVES) * 2;
    constexpr int C_BYTES  = ROWS * LDC * 4;
    constexpr int SM_BYTES = AB_BYTES > C_BYTES ? AB_BYTES : C_BYTES;
    __shared__ __align__(16) char smem[SM_BYTES];
    __shared__ float s_sc[64], s_sh[64];
    half*  Ah = (half*)smem;
    half*  Al = Ah + A_HALVES;
    half*  Wh = Al + A_HALVES;
    half*  Wl = Wh + W_HALVES;
    float* Cs = (float*)smem;

    int tid = threadIdx.x;
    int warp = tid >> 5;
    if (zsoff >= 0 && blockIdx.x == 0) d_stats[zsoff + tid] = 0.f;

    if (BNIN && tid < 64) {
        float invM = 1.f / (float)M;
        float mu  = d_stats[bnoff + tid] * invM;
        float var = d_stats[bnoff + 64 + tid] * invM - mu * mu;
        float sc  = rsqrtf(var + 1e-5f) * g[tid];
        s_sc[tid] = sc;
        s_sh[tid] = bt[tid] - mu * sc;
    }
    if (BNIN) __syncthreads();

    const float* A = USE_X ? A_ext : d_hbuf;
    int m0 = blockIdx.x * ROWS;
    int r_local = tid >> 1;
    int row = m0 + r_local;
    bool rv = row < M;
    int ac0 = (tid & 1) * 16;

    float4 Areg[4];
    float4 Wreg[WF4];

#pragma unroll
    for (int j = 0; j < 4; j++)
        Areg[j] = rv ? *(const float4*)(A + (size_t)row * K + ac0 + j * 4)
                     : make_float4(0.f, 0.f, 0.f, 0.f);
#pragma unroll
    for (int j = 0; j < WF4; j++)
        Wreg[j] = ((const float4*)Wm)[j * 128 + tid];

    wmma::fragment<wmma::accumulator, 16, 16, 16, float> acc[NC / 16];
#pragma unroll
    for (int j = 0; j < NC / 16; j++) wmma::fill_fragment(acc[j], 0.f);

#pragma unroll
    for (int c = 0; c < NCHUNK; c++) {
#pragma unroll
        for (int j = 0; j < WF4; j++) {
            int f = j * 128 + tid;
            int wr = (f * 4) / NC, wc = (f * 4) % NC;
            half2 h0, l0, h1, l1;
            split_h2(Wreg[j].x, Wreg[j].y, h0, l0);
            split_h2(Wreg[j].z, Wreg[j].w, h1, l1);
            *(uint2*)(Wh + wr * LDB + wc) = make_uint2(h2u(h0), h2u(h1));
            *(uint2*)(Wl + wr * LDB + wc) = make_uint2(h2u(l0), h2u(l1));
        }
#pragma unroll
        for (int j = 0; j < 4; j++) {
            float4 a = Areg[j];
            if (BNIN) {
                int cc = c * CH + ac0 + j * 4;
                a.x = fmaxf(fmaf(a.x, s_sc[cc + 0], s_sh[cc + 0]), 0.f);
                a.y = fmaxf(fmaf(a.y, s_sc[cc + 1], s_sh[cc + 1]), 0.f);
                a.z = fmaxf(fmaf(a.z, s_sc[cc + 2], s_sh[cc + 2]), 0.f);
                a.w = fmaxf(fmaf(a.w, s_sc[cc + 3], s_sh[cc + 3]), 0.f);
            }
            half2 h0, l0, h1, l1;
            split_h2(a.x, a.y, h0, l0);
            split_h2(a.z, a.w, h1, l1);
            int cc = ac0 + j * 4;
            *(uint2*)(Ah + r_local * LDA + cc) = make_uint2(h2u(h0), h2u(h1));
            *(uint2*)(Al + r_local * LDA + cc) = make_uint2(h2u(l0), h2u(l1));
        }
        __syncthreads();

        if (c + 1 < NCHUNK) {
            int kc = (c + 1) * CH;
#pragma unroll
            for (int j = 0; j < 4; j++)
                Areg[j] = rv ? *(const float4*)(A + (size_t)row * K + kc + ac0 + j * 4)
                             : make_float4(0.f, 0.f, 0.f, 0.f);
#pragma unroll
            for (int j = 0; j < WF4; j++)
                Wreg[j] = ((const float4*)(Wm + (size_t)kc * NC))[j * 128 + tid];
        }

#pragma unroll
        for (int k = 0; k < CH; k += 16) {
            wmma::fragment<wmma::matrix_a, 16, 16, 16, half, wmma::row_major> afh, afl;
            wmma::load_matrix_sync(afh, Ah + (warp * 16) * LDA + k, LDA);
            wmma::load_matrix_sync(afl, Al + (warp * 16) * LDA + k, LDA);
#pragma unroll
            for (int j = 0; j < NC / 16; j++) {
                wmma::fragment<wmma::matrix_b, 16, 16, 16, half, wmma::row_major> bfh, bfl;
                wmma::load_matrix_sync(bfh, Wh + k * LDB + j * 16, LDB);
                wmma::load_matrix_sync(bfl, Wl + k * LDB + j * 16, LDB);
                wmma::mma_sync(acc[j], afh, bfh, acc[j]);
                wmma::mma_sync(acc[j], afh, bfl, acc[j]);
                wmma::mma_sync(acc[j], afl, bfh, acc[j]);
            }
        }
        __syncthreads();
    }

#pragma unroll
    for (int j = 0; j < NC / 16; j++)
        wmma::store_matrix_sync(Cs + (warp * 16) * LDC + j * 16, acc[j], LDC,
                                wmma::mem_row_major);
    __syncwarp();

    int r = tid >> 1;
    int orow = m0 + r;
    if (!DOT) {
        __half2* hwh = (__half2*)d_hw;
        int c0 = (tid & 1) * 32;
        if (orow < M) {
#pragma unroll
            for (int j = 0; j < 32; j += 8) {
                float4 v0 = *(float4*)&Cs[r * LDC + c0 + j];
                float4 v1 = *(float4*)&Cs[r * LDC + c0 + j + 4];
                __half2 p0 = __floats2half2_rn(v0.x, v0.y);
                __half2 p1 = __floats2half2_rn(v0.z, v0.w);
                __half2 p2 = __floats2half2_rn(v1.x, v1.y);
                __half2 p3 = __floats2half2_rn(v1.z, v1.w);
                uint4 u;
                u.x = *(unsigned*)&p0;
                u.y = *(unsigned*)&p1;
                u.z = *(unsigned*)&p2;
                u.w = *(unsigned*)&p3;
                *(uint4*)(hwh + (size_t)orow * 32 + (c0 + j) / 2) = u;
            }
        }
    } else {
        int c0 = (tid & 1) * 16;
        float p = 0.f;
#pragma unroll
        for (int j = 0; j < 16; j++)
            p = fmaf(fmaxf(Cs[r * LDC + c0 + j] + lb1[c0 + j], 0.f), lw2[c0 + j], p);
        p += __shfl_xor_sync(0xffffffffu, p, 1);
        if ((tid & 1) == 0 && orow < M) out[orow] = p + lb2[0];
    }
}

// ---------------- aggregation: warp/node, half-warp split, 4 edges in flight ----------------
// __launch_bounds__(512, 2): 64-reg cap so the quad unroll does NOT spill (R11 lesson).
__global__ void __launch_bounds__(512, 2) agg_kernel(int N, int sb) {
    __shared__ float s_sum[16][65];
    __shared__ float s_sq[16][65];
    const uint2* hw4 = (const uint2*)d_hw;
    float4* out4 = (float4*)d_hbuf;
    int warp = threadIdx.x >> 5;
    int lane = threadIdx.x & 31;
    int h  = lane >> 4;
    int lq = lane & 15;
    int node = blockIdx.x * 16 + warp;
    float4 acc = make_float4(0.f, 0.f, 0.f, 0.f);
    if (node < N) {
        int s = d_off[node], e = d_off[node + 1];
        int i = s + h;
        for (; i + 6 < e; i += 8) {
            int2 e0 = d_csr[i];
            int2 e1 = d_csr[i + 2];
            int2 e2 = d_csr[i + 4];
            int2 e3 = d_csr[i + 6];
            uint2 r0 = hw4[(size_t)e0.x * 16 + lq];
            uint2 r1 = hw4[(size_t)e1.x * 16 + lq];
            uint2 r2 = hw4[(size_t)e2.x * 16 + lq];
            uint2 r3 = hw4[(size_t)e3.x * 16 + lq];
            float w0 = __int_as_float(e0.y);
            float w1 = __int_as_float(e1.y);
            float w2 = __int_as_float(e2.y);
            float w3 = __int_as_float(e3.y);
            float2 a0 = __half22float2(*(__half2*)&r0.x), b0 = __half22float2(*(__half2*)&r0.y);
            float2 a1 = __half22float2(*(__half2*)&r1.x), b1 = __half22float2(*(__half2*)&r1.y);
            float2 a2 = __half22float2(*(__half2*)&r2.x), b2 = __half22float2(*(__half2*)&r2.y);
            float2 a3 = __half22float2(*(__half2*)&r3.x), b3 = __half22float2(*(__half2*)&r3.y);
            acc.x = fmaf(w0, a0.x, acc.x); acc.y = fmaf(w0, a0.y, acc.y);
            acc.z = fmaf(w0, b0.x, acc.z); acc.w = fmaf(w0, b0.y, acc.w);
            acc.x = fmaf(w1, a1.x, acc.x); acc.y = fmaf(w1, a1.y, acc.y);
            acc.z = fmaf(w1, b1.x, acc.z); acc.w = fmaf(w1, b1.y, acc.w);
            acc.x = fmaf(w2, a2.x, acc.x); acc.y = fmaf(w2, a2.y, acc.y);
            acc.z = fmaf(w2, b2.x, acc.z); acc.w = fmaf(w2, b2.y, acc.w);
            acc.x = fmaf(w3, a3.x, acc.x); acc.y = fmaf(w3, a3.y, acc.y);
            acc.z = fmaf(w3, b3.x, acc.z); acc.w = fmaf(w3, b3.y, acc.w);
        }
        for (; i < e; i += 2) {
            int2 e0 = d_csr[i];
            uint2 r0 = hw4[(size_t)e0.x * 16 + lq];
            float w0 = __int_as_float(e0.y);
            float2 a0 = __half22float2(*(__half2*)&r0.x), b0 = __half22float2(*(__half2*)&r0.y);
            acc.x = fmaf(w0, a0.x, acc.x); acc.y = fmaf(w0, a0.y, acc.y);
            acc.z = fmaf(w0, b0.x, acc.z); acc.w = fmaf(w0, b0.y, acc.w);
        }
    }
    acc.x += __shfl_xor_sync(0xffffffffu, acc.x, 16);
    acc.y += __shfl_xor_sync(0xffffffffu, acc.y, 16);
    acc.z += __shfl_xor_sync(0xffffffffu, acc.z, 16);
    acc.w += __shfl_xor_sync(0xffffffffu, acc.w, 16);
    if (node < N && h == 0) {
        float dv = d_dinv[node];
        float sw = dv * dv;
        uint2 rv = hw4[(size_t)node * 16 + lq];
        float2 a = __half22float2(*(__half2*)&rv.x);
        float2 b = __half22float2(*(__half2*)&rv.y);
        acc.x = fmaf(sw, a.x, acc.x);
        acc.y = fmaf(sw, a.y, acc.y);
        acc.z = fmaf(sw, b.x, acc.z);
        acc.w = fmaf(sw, b.y, acc.w);
        out4[(size_t)node * 16 + lq] = acc;
    }
    if (h == 0) {
        int c = lq * 4;
        bool v = node < N;
        s_sum[warp][c + 0] = v ? acc.x : 0.f;
        s_sum[warp][c + 1] = v ? acc.y : 0.f;
        s_sum[warp][c + 2] = v ? acc.z : 0.f;
        s_sum[warp][c + 3] = v ? acc.w : 0.f;
        s_sq[warp][c + 0]  = v ? acc.x * acc.x : 0.f;
        s_sq[warp][c + 1]  = v ? acc.y * acc.y : 0.f;
        s_sq[warp][c + 2]  = v ? acc.z * acc.z : 0.f;
        s_sq[warp][c + 3]  = v ? acc.w * acc.w : 0.f;
    }
    __syncthreads();
    if (threadIdx.x < 64) {
        int c = threadIdx.x;
        float t = 0.f, q = 0.f;
#pragma unroll
        for (int w = 0; w < 16; w++) { t += s_sum[w][c]; q += s_sq[w][c]; }
        atomicAdd(&d_stats[sb + c], t);
        atomicAdd(&d_stats[sb + 64 + c], q);
    }
}

// ---------------- host orchestration (kernel launches + capture-legal fork/join) ----------------
extern "C" void kernel_launch(void* const* d_in, const int* in_sizes, int n_in,
                              void* d_out, int out_size) {
    const float* x   = (const float*)d_in[0];
    const int*   ei  = (const int*)d_in[1];
    const float* W0  = (const float*)d_in[2];
    const float* g0  = (const float*)d_in[4];
    const float* bt0 = (const float*)d_in[5];
    const float* W1  = (const float*)d_in[6];
    const float* g1  = (const float*)d_in[8];
    const float* bt1 = (const float*)d_in[9];
    const float* W2  = (const float*)d_in[10];
    const float* g2  = (const float*)d_in[12];
    const float* bt2 = (const float*)d_in[13];
    const float* lw1 = (const float*)d_in[14];
    const float* lb1 = (const float*)d_in[15];
    const float* lw2 = (const float*)d_in[16];
    const float* lb2 = (const float*)d_in[17];
    float* out = (float*)d_out;

    int N = out_size;
    int E = in_sizes[1] / 2;
    if (N > MAXN || E > MAXE) return;

    const int* src = ei;
    const int* dst = ei + E;

    int bN = (N + 255) / 256;
    int bE = (E + 255) / 256;
    int G  = (N + 1023) / 1024;
    int gB   = (N + 63) / 64;
    int aggB = (N + 15) / 16;

    if (g_si.ok) {
        // fork: CSR pipeline on aux stream, gemm0 on main stream (disjoint data)
        cudaEventRecord(g_si.ef, 0);
        cudaStreamWaitEvent(g_si.s, g_si.ef, 0);
        zero_kernel<<<bN, 256, 0, g_si.s>>>(N);
        hist_kernel<<<bE, 256, 0, g_si.s>>>(dst, E);
        scanA_kernel<<<G, 256, 0, g_si.s>>>(N);
        scanC_kernel<<<G, 256, 0, g_si.s>>>(G, N);
        scatter_kernel<<<bE, 256, 0, g_si.s>>>(src, dst, E);
        gemm_kernel<128, 64, true, false, false><<<gB, 128>>>(
            x, W0, nullptr, nullptr, nullptr, nullptr, nullptr, nullptr, N, 0, 0);
        cudaEventRecord(g_si.ej, g_si.s);
        cudaStreamWaitEvent(0, g_si.ej, 0);
    } else {
        zero_kernel<<<bN, 256>>>(N);
        hist_kernel<<<bE, 256>>>(dst, E);
        scanA_kernel<<<G, 256>>>(N);
        gemm_kernel<128, 64, true, false, false><<<gB, 128>>>(
            x, W0, nullptr, nullptr, nullptr, nullptr, nullptr, nullptr, N, 0, 0);
        scanC_kernel<<<G, 256>>>(G, N);
        scatter_kernel<<<bE, 256>>>(src, dst, E);
    }

    // L0 agg -> hbuf + stats buf0
    agg_kernel<<<aggB, 512>>>(N, 0);

    // L1: BN0(hbuf) @ W1 -> hw fp16 (zero buf1); agg -> stats buf1
    gemm_kernel<64, 64, false, true, false><<<gB, 128>>>(
        nullptr, W1, g0, bt0, nullptr, nullptr, nullptr, nullptr, N, 0, 128);
    agg_kernel<<<aggB, 512>>>(N, 128);

    // L2: BN1(hbuf) @ W2 -> hw fp16 (zero buf0); agg -> stats buf0
    gemm_kernel<64, 64, false, true, false><<<gB, 128>>>(
        nullptr, W2, g1, bt1, nullptr, nullptr, nullptr, nullptr, N, 128, 0);
    agg_kernel<<<aggB, 512>>>(N, 0);

    // MLP head fused: relu(BN2(hbuf) @ lw1 + lb1) . lw2 + lb2 -> out
    gemm_kernel<64, 32, false, true, true><<<gB, 128>>>(
        nullptr, lw1, g2, bt2, lb1, lw2, lb2, out, N, 0, -1);
}

// round 15
// speedup vs baseline: 1.1594x; 1.1594x over previous
#include <cuda_runtime.h>
#include <cuda_fp16.h>
#include <mma.h>
using namespace nvcuda;

#define MAXN 100000
#define MAXE 1600000
#define HIDF 64

// ---------------- static device scratch ----------------
__device__ __align__(16) float d_hw[(size_t)MAXN * HIDF];    // fp16 rows (N x 64 halves)
__device__ __align__(16) float d_hbuf[(size_t)MAXN * HIDF];  // aggregated features fp32
__device__ int   d_cnt[MAXN];
__device__ int   d_fill[MAXN];
__device__ int   d_off[MAXN + 1];
__device__ float d_dinv[MAXN];
__device__ int2  d_csr[MAXE];
__device__ int   d_bsum[128];
__device__ float d_stats[256];      // two dense buffers of 128: [sum64|sumsq64] x2

// ---- aux stream/events, created pre-main (outside any mem checkpoint / capture) ----
struct StreamInit {
    cudaStream_t s = nullptr;
    cudaEvent_t  ef = nullptr, ej = nullptr;
    bool ok = false;
    StreamInit() {
        if (cudaStreamCreateWithFlags(&s, cudaStreamNonBlocking) == cudaSuccess &&
            cudaEventCreateWithFlags(&ef, cudaEventDisableTiming) == cudaSuccess &&
            cudaEventCreateWithFlags(&ej, cudaEventDisableTiming) == cudaSuccess)
            ok = true;
    }
};
static StreamInit g_si;

// ---------------- CSR construction ----------------
__global__ void zero_kernel(int N) {
    int i = blockIdx.x * blockDim.x + threadIdx.x;
    if (i < N) d_cnt[i] = 0;
}

__global__ void hist_kernel(const int* __restrict__ dst, int E) {
    int i = blockIdx.x * blockDim.x + threadIdx.x;
    if (i < E) atomicAdd(&d_cnt[dst[i]], 1);
}

__global__ void scanA_kernel(int N) {
    __shared__ int sh[256];
    int base = blockIdx.x * 1024 + threadIdx.x * 4;
    int t = 0;
#pragma unroll
    for (int j = 0; j < 4; j++) {
        int i = base + j;
        if (i < N) {
            int c = d_cnt[i];
            t += c;
            d_dinv[i] = rsqrtf((float)(c + 1));
        }
    }
    sh[threadIdx.x] = t;
    __syncthreads();
    for (int o = 128; o > 0; o >>= 1) {
        if (threadIdx.x < o) sh[threadIdx.x] += sh[threadIdx.x + o];
        __syncthreads();
    }
    if (threadIdx.x == 0) d_bsum[blockIdx.x] = sh[0];
}

__global__ void scanC_kernel(int G, int N) {
    __shared__ int sh[256];
    __shared__ int bs[128];
    __shared__ int bprefix;
    int tid = threadIdx.x;
    if (tid < G) bs[tid] = d_bsum[tid];
    __syncthreads();
    if (tid == 0) {
        int p = 0;
        for (int b = 0; b < (int)blockIdx.x; b++) p += bs[b];
        bprefix = p;
    }
    int base = blockIdx.x * 1024 + tid * 4;
    int v[4]; int t = 0;
#pragma unroll
    for (int j = 0; j < 4; j++) { v[j] = (base + j < N) ? d_cnt[base + j] : 0; t += v[j]; }
    sh[tid] = t;
    __syncthreads();
    for (int o = 1; o < 256; o <<= 1) {
        int x = (tid >= o) ? sh[tid - o] : 0;
        __syncthreads();
        sh[tid] += x;
        __syncthreads();
    }
    int excl = sh[tid] - t + bprefix;
#pragma unroll
    for (int j = 0; j < 4; j++) {
        if (base + j < N) { d_off[base + j] = excl; d_fill[base + j] = 0; excl += v[j]; }
    }
    if ((int)blockIdx.x == G - 1 && tid == 255) d_off[N] = bprefix + sh[255];
}

__global__ void scatter_kernel(const int* __restrict__ src,
                               const int* __restrict__ dst, int E) {
    int i = blockIdx.x * blockDim.x + threadIdx.x;
    if (i >= E) return;
    int s = src[i];
    int d = dst[i];
    int pos = d_off[d] + atomicAdd(&d_fill[d], 1);
    float w = d_dinv[s] * d_dinv[d];
    d_csr[pos] = make_int2(s, __float_as_int(w));
}

__device__ __forceinline__ void split_h2(float a, float b, half2& hi, half2& lo) {
    half2 h = __floats2half2_rn(a, b);
    float2 hf = __half22float2(h);
    hi = h;
    lo = __floats2half2_rn(a - hf.x, b - hf.y);
}

__device__ __forceinline__ unsigned h2u(half2 h) { return *(unsigned*)&h; }

// ---------------- split-fp16 wmma GEMM, register-prefetch pipelined ----------------
template <int K, int NC, bool USE_X, bool BNIN, bool DOT>
__global__ void __launch_bounds__(128) gemm_kernel(
        const float* __restrict__ A_ext, const float* __restrict__ Wm,
        const float* __restrict__ g, const float* __restrict__ bt,
        const float* __restrict__ lb1, const float* __restrict__ lw2,
        const float* __restrict__ lb2, float* __restrict__ out,
        int M, int bnoff, int zsoff) {
    constexpr int ROWS = 64;
    constexpr int CH = 32;
    constexpr int NCHUNK = K / CH;
    constexpr int LDA = CH + 8;
    constexpr int LDB = NC + 8;
    constexpr int LDC = NC + 4;
    constexpr int WF4 = CH * NC / (4 * 128);
    constexpr int A_HALVES = ROWS * LDA;
    constexpr int W_HALVES = CH * LDB;
    constexpr int AB_BYTES = (2 * A_HALVES + 2 * W_HALVES) * 2;
    constexpr int C_BYTES  = ROWS * LDC * 4;
    constexpr int SM_BYTES = AB_BYTES > C_BYTES ? AB_BYTES : C_BYTES;
    __shared__ __align__(16) char smem[SM_BYTES];
    __shared__ float s_sc[64], s_sh[64];
    half*  Ah = (half*)smem;
    half*  Al = Ah + A_HALVES;
    half*  Wh = Al + A_HALVES;
    half*  Wl = Wh + W_HALVES;
    float* Cs = (float*)smem;

    int tid = threadIdx.x;
    int warp = tid >> 5;
    if (zsoff >= 0 && blockIdx.x == 0) d_stats[zsoff + tid] = 0.f;

    if (BNIN && tid < 64) {
        float invM = 1.f / (float)M;
        float mu  = d_stats[bnoff + tid] * invM;
        float var = d_stats[bnoff + 64 + tid] * invM - mu * mu;
        float sc  = rsqrtf(var + 1e-5f) * g[tid];
        s_sc[tid] = sc;
        s_sh[tid] = bt[tid] - mu * sc;
    }
    if (BNIN) __syncthreads();

    const float* A = USE_X ? A_ext : d_hbuf;
    int m0 = blockIdx.x * ROWS;
    int r_local = tid >> 1;
    int row = m0 + r_local;
    bool rv = row < M;
    int ac0 = (tid & 1) * 16;

    float4 Areg[4];
    float4 Wreg[WF4];

#pragma unroll
    for (int j = 0; j < 4; j++)
        Areg[j] = rv ? *(const float4*)(A + (size_t)row * K + ac0 + j * 4)
                     : make_float4(0.f, 0.f, 0.f, 0.f);
#pragma unroll
    for (int j = 0; j < WF4; j++)
        Wreg[j] = ((const float4*)Wm)[j * 128 + tid];

    wmma::fragment<wmma::accumulator, 16, 16, 16, float> acc[NC / 16];
#pragma unroll
    for (int j = 0; j < NC / 16; j++) wmma::fill_fragment(acc[j], 0.f);

#pragma unroll
    for (int c = 0; c < NCHUNK; c++) {
#pragma unroll
        for (int j = 0; j < WF4; j++) {
            int f = j * 128 + tid;
            int wr = (f * 4) / NC, wc = (f * 4) % NC;
            half2 h0, l0, h1, l1;
            split_h2(Wreg[j].x, Wreg[j].y, h0, l0);
            split_h2(Wreg[j].z, Wreg[j].w, h1, l1);
            *(uint2*)(Wh + wr * LDB + wc) = make_uint2(h2u(h0), h2u(h1));
            *(uint2*)(Wl + wr * LDB + wc) = make_uint2(h2u(l0), h2u(l1));
        }
#pragma unroll
        for (int j = 0; j < 4; j++) {
            float4 a = Areg[j];
            if (BNIN) {
                int cc = c * CH + ac0 + j * 4;
                a.x = fmaxf(fmaf(a.x, s_sc[cc + 0], s_sh[cc + 0]), 0.f);
                a.y = fmaxf(fmaf(a.y, s_sc[cc + 1], s_sh[cc + 1]), 0.f);
                a.z = fmaxf(fmaf(a.z, s_sc[cc + 2], s_sh[cc + 2]), 0.f);
                a.w = fmaxf(fmaf(a.w, s_sc[cc + 3], s_sh[cc + 3]), 0.f);
            }
            half2 h0, l0, h1, l1;
            split_h2(a.x, a.y, h0, l0);
            split_h2(a.z, a.w, h1, l1);
            int cc = ac0 + j * 4;
            *(uint2*)(Ah + r_local * LDA + cc) = make_uint2(h2u(h0), h2u(h1));
            *(uint2*)(Al + r_local * LDA + cc) = make_uint2(h2u(l0), h2u(l1));
        }
        __syncthreads();

        if (c + 1 < NCHUNK) {
            int kc = (c + 1) * CH;
#pragma unroll
            for (int j = 0; j < 4; j++)
                Areg[j] = rv ? *(const float4*)(A + (size_t)row * K + kc + ac0 + j * 4)
                             : make_float4(0.f, 0.f, 0.f, 0.f);
#pragma unroll
            for (int j = 0; j < WF4; j++)
                Wreg[j] = ((const float4*)(Wm + (size_t)kc * NC))[j * 128 + tid];
        }

#pragma unroll
        for (int k = 0; k < CH; k += 16) {
            wmma::fragment<wmma::matrix_a, 16, 16, 16, half, wmma::row_major> afh, afl;
            wmma::load_matrix_sync(afh, Ah + (warp * 16) * LDA + k, LDA);
            wmma::load_matrix_sync(afl, Al + (warp * 16) * LDA + k, LDA);
#pragma unroll
            for (int j = 0; j < NC / 16; j++) {
                wmma::fragment<wmma::matrix_b, 16, 16, 16, half, wmma::row_major> bfh, bfl;
                wmma::load_matrix_sync(bfh, Wh + k * LDB + j * 16, LDB);
                wmma::load_matrix_sync(bfl, Wl + k * LDB + j * 16, LDB);
                wmma::mma_sync(acc[j], afh, bfh, acc[j]);
                wmma::mma_sync(acc[j], afh, bfl, acc[j]);
                wmma::mma_sync(acc[j], afl, bfh, acc[j]);
            }
        }
        __syncthreads();
    }

#pragma unroll
    for (int j = 0; j < NC / 16; j++)
        wmma::store_matrix_sync(Cs + (warp * 16) * LDC + j * 16, acc[j], LDC,
                                wmma::mem_row_major);
    __syncwarp();

    int r = tid >> 1;
    int orow = m0 + r;
    if (!DOT) {
        __half2* hwh = (__half2*)d_hw;
        int c0 = (tid & 1) * 32;
        if (orow < M) {
#pragma unroll
            for (int j = 0; j < 32; j += 8) {
                float4 v0 = *(float4*)&Cs[r * LDC + c0 + j];
                float4 v1 = *(float4*)&Cs[r * LDC + c0 + j + 4];
                __half2 p0 = __floats2half2_rn(v0.x, v0.y);
                __half2 p1 = __floats2half2_rn(v0.z, v0.w);
                __half2 p2 = __floats2half2_rn(v1.x, v1.y);
                __half2 p3 = __floats2half2_rn(v1.z, v1.w);
                uint4 u;
                u.x = *(unsigned*)&p0;
                u.y = *(unsigned*)&p1;
                u.z = *(unsigned*)&p2;
                u.w = *(unsigned*)&p3;
                *(uint4*)(hwh + (size_t)orow * 32 + (c0 + j) / 2) = u;
            }
        }
    } else {
        int c0 = (tid & 1) * 16;
        float p = 0.f;
#pragma unroll
        for (int j = 0; j < 16; j++)
            p = fmaf(fmaxf(Cs[r * LDC + c0 + j] + lb1[c0 + j], 0.f), lw2[c0 + j], p);
        p += __shfl_xor_sync(0xffffffffu, p, 1);
        if ((tid & 1) == 0 && orow < M) out[orow] = p + lb2[0];
    }
}

// ---------------- aggregation: warp per node, 2 edges/warp via half-warps, 8B loads ----------------
// R13 exact form: __launch_bounds__(512, 3) = 48 warps/SM (occupancy > per-thread ILP here)
__global__ void __launch_bounds__(512, 3) agg_kernel(int N, int sb) {
    __shared__ float s_sum[16][65];
    __shared__ float s_sq[16][65];
    const uint2* hw4 = (const uint2*)d_hw;
    float4* out4 = (float4*)d_hbuf;
    int warp = threadIdx.x >> 5;
    int lane = threadIdx.x & 31;
    int h  = lane >> 4;
    int lq = lane & 15;
    int node = blockIdx.x * 16 + warp;
    float4 acc = make_float4(0.f, 0.f, 0.f, 0.f);
    if (node < N) {
        int s = d_off[node], e = d_off[node + 1];
        int i = s + h;
        for (; i + 2 < e; i += 4) {
            int2 e0 = d_csr[i];
            int2 e1 = d_csr[i + 2];
            uint2 r0 = hw4[(size_t)e0.x * 16 + lq];
            uint2 r1 = hw4[(size_t)e1.x * 16 + lq];
            float w0 = __int_as_float(e0.y);
            float w1 = __int_as_float(e1.y);
            float2 a0 = __half22float2(*(__half2*)&r0.x);
            float2 b0 = __half22float2(*(__half2*)&r0.y);
            float2 a1 = __half22float2(*(__half2*)&r1.x);
            float2 b1 = __half22float2(*(__half2*)&r1.y);
            acc.x = fmaf(w0, a0.x, acc.x);
            acc.y = fmaf(w0, a0.y, acc.y);
            acc.z = fmaf(w0, b0.x, acc.z);
            acc.w = fmaf(w0, b0.y, acc.w);
            acc.x = fmaf(w1, a1.x, acc.x);
            acc.y = fmaf(w1, a1.y, acc.y);
            acc.z = fmaf(w1, b1.x, acc.z);
            acc.w = fmaf(w1, b1.y, acc.w);
        }
        if (i < e) {
            int2 e0 = d_csr[i];
            uint2 r0 = hw4[(size_t)e0.x * 16 + lq];
            float w0 = __int_as_float(e0.y);
            float2 a0 = __half22float2(*(__half2*)&r0.x);
            float2 b0 = __half22float2(*(__half2*)&r0.y);
            acc.x = fmaf(w0, a0.x, acc.x);
            acc.y = fmaf(w0, a0.y, acc.y);
            acc.z = fmaf(w0, b0.x, acc.z);
            acc.w = fmaf(w0, b0.y, acc.w);
        }
    }
    acc.x += __shfl_xor_sync(0xffffffffu, acc.x, 16);
    acc.y += __shfl_xor_sync(0xffffffffu, acc.y, 16);
    acc.z += __shfl_xor_sync(0xffffffffu, acc.z, 16);
    acc.w += __shfl_xor_sync(0xffffffffu, acc.w, 16);
    if (node < N && h == 0) {
        float dv = d_dinv[node];
        float sw = dv * dv;
        uint2 rv = hw4[(size_t)node * 16 + lq];
        float2 a = __half22float2(*(__half2*)&rv.x);
        float2 b = __half22float2(*(__half2*)&rv.y);
        acc.x = fmaf(sw, a.x, acc.x);
        acc.y = fmaf(sw, a.y, acc.y);
        acc.z = fmaf(sw, b.x, acc.z);
        acc.w = fmaf(sw, b.y, acc.w);
        out4[(size_t)node * 16 + lq] = acc;
    }
    if (h == 0) {
        int c = lq * 4;
        bool v = node < N;
        s_sum[warp][c + 0] = v ? acc.x : 0.f;
        s_sum[warp][c + 1] = v ? acc.y : 0.f;
        s_sum[warp][c + 2] = v ? acc.z : 0.f;
        s_sum[warp][c + 3] = v ? acc.w : 0.f;
        s_sq[warp][c + 0]  = v ? acc.x * acc.x : 0.f;
        s_sq[warp][c + 1]  = v ? acc.y * acc.y : 0.f;
        s_sq[warp][c + 2]  = v ? acc.z * acc.z : 0.f;
        s_sq[warp][c + 3]  = v ? acc.w * acc.w : 0.f;
    }
    __syncthreads();
    if (threadIdx.x < 64) {
        int c = threadIdx.x;
        float t = 0.f, q = 0.f;
#pragma unroll
        for (int w = 0; w < 16; w++) { t += s_sum[w][c]; q += s_sq[w][c]; }
        atomicAdd(&d_stats[sb + c], t);
        atomicAdd(&d_stats[sb + 64 + c], q);
    }
}

// ---------------- host orchestration (kernel launches + capture-legal fork/join) ----------------
extern "C" void kernel_launch(void* const* d_in, const int* in_sizes, int n_in,
                              void* d_out, int out_size) {
    const float* x   = (const float*)d_in[0];
    const int*   ei  = (const int*)d_in[1];
    const float* W0  = (const float*)d_in[2];
    const float* g0  = (const float*)d_in[4];
    const float* bt0 = (const float*)d_in[5];
    const float* W1  = (const float*)d_in[6];
    const float* g1  = (const float*)d_in[8];
    const float* bt1 = (const float*)d_in[9];
    const float* W2  = (const float*)d_in[10];
    const float* g2  = (const float*)d_in[12];
    const float* bt2 = (const float*)d_in[13];
    const float* lw1 = (const float*)d_in[14];
    const float* lb1 = (const float*)d_in[15];
    const float* lw2 = (const float*)d_in[16];
    const float* lb2 = (const float*)d_in[17];
    float* out = (float*)d_out;

    int N = out_size;
    int E = in_sizes[1] / 2;
    if (N > MAXN || E > MAXE) return;

    const int* src = ei;
    const int* dst = ei + E;

    int bN = (N + 255) / 256;
    int bE = (E + 255) / 256;
    int G  = (N + 1023) / 1024;
    int gB   = (N + 63) / 64;
    int aggB = (N + 15) / 16;

    if (g_si.ok) {
        // fork: CSR pipeline on aux stream, gemm0 on main stream (disjoint data)
        cudaEventRecord(g_si.ef, 0);
        cudaStreamWaitEvent(g_si.s, g_si.ef, 0);
        zero_kernel<<<bN, 256, 0, g_si.s>>>(N);
        hist_kernel<<<bE, 256, 0, g_si.s>>>(dst, E);
        scanA_kernel<<<G, 256, 0, g_si.s>>>(N);
        scanC_kernel<<<G, 256, 0, g_si.s>>>(G, N);
        scatter_kernel<<<bE, 256, 0, g_si.s>>>(src, dst, E);
        gemm_kernel<128, 64, true, false, false><<<gB, 128>>>(
            x, W0, nullptr, nullptr, nullptr, nullptr, nullptr, nullptr, N, 0, 0);
        cudaEventRecord(g_si.ej, g_si.s);
        cudaStreamWaitEvent(0, g_si.ej, 0);
    } else {
        zero_kernel<<<bN, 256>>>(N);
        hist_kernel<<<bE, 256>>>(dst, E);
        scanA_kernel<<<G, 256>>>(N);
        gemm_kernel<128, 64, true, false, false><<<gB, 128>>>(
            x, W0, nullptr, nullptr, nullptr, nullptr, nullptr, nullptr, N, 0, 0);
        scanC_kernel<<<G, 256>>>(G, N);
        scatter_kernel<<<bE, 256>>>(src, dst, E);
    }

    // L0 agg -> hbuf + stats buf0
    agg_kernel<<<aggB, 512>>>(N, 0);

    // L1: BN0(hbuf) @ W1 -> hw fp16 (zero buf1); agg -> stats buf1
    gemm_kernel<64, 64, false, true, false><<<gB, 128>>>(
        nullptr, W1, g0, bt0, nullptr, nullptr, nullptr, nullptr, N, 0, 128);
    agg_kernel<<<aggB, 512>>>(N, 128);

    // L2: BN1(hbuf) @ W2 -> hw fp16 (zero buf0); agg -> stats buf0
    gemm_kernel<64, 64, false, true, false><<<gB, 128>>>(
        nullptr, W2, g1, bt1, nullptr, nullptr, nullptr, nullptr, N, 128, 0);
    agg_kernel<<<aggB, 512>>>(N, 0);

    // MLP head fused: relu(BN2(hbuf) @ lw1 + lb1) . lw2 + lb2 -> out
    gemm_kernel<64, 32, false, true, true><<<gB, 128>>>(
        nullptr, lw1, g2, bt2, lb1, lw2, lb2, out, N, 0, -1);
}